// round 16
// baseline (speedup 1.0000x reference)
#include <cuda_runtime.h>
#include <math.h>

#define SEQN 64
#define BSN  32
#define NHID 256
#define G4   1024

#define TK        16
#define ND        3
#define TILEB     (TK * G4 * 4)
#define NT_STEP   (NHID / TK)
#define NT_TOT    (SEQN * NT_STEP)
#define NTHR      288

__device__ float  g_Gx[BSN * SEQN * G4];
__device__ float4 g_Wt[256 * 256];
__device__ float  g_state_f[BSN * NHID * 64];
__device__ float  g_part[BSN * 2];

typedef unsigned long long ull;

__device__ __forceinline__ ull pk2(float a, float b) {
    ull r;
    asm("mov.b64 %0, {%1, %2};" : "=l"(r) : "f"(a), "f"(b));
    return r;
}
__device__ __forceinline__ float2 upk2(ull v) {
    float2 r;
    asm("mov.b64 {%0, %1}, %2;" : "=f"(r.x), "=f"(r.y) : "l"(v));
    return r;
}
__device__ __forceinline__ void fma2(ull& acc, ull a, ull b) {
    asm("fma.rn.f32x2 %0, %1, %2, %0;" : "+l"(acc) : "l"(a), "l"(b));
}
__device__ __forceinline__ float tanha(float x) {
    float r;
    asm("tanh.approx.f32 %0, %1;" : "=f"(r) : "f"(x));
    return r;
}
__device__ __forceinline__ float siga(float x) {
    return fmaf(0.5f, tanha(0.5f * x), 0.5f);
}

__device__ __forceinline__ unsigned smem_u32(const void* p) {
    unsigned a;
    asm("{ .reg .u64 t; cvta.to.shared.u64 t, %1; cvt.u32.u64 %0, t; }"
        : "=r"(a) : "l"(p));
    return a;
}
__device__ __forceinline__ void mbar_init(unsigned mbar, unsigned cnt) {
    asm volatile("mbarrier.init.shared.b64 [%0], %1;" :: "r"(mbar), "r"(cnt) : "memory");
}
__device__ __forceinline__ void mbar_expect_tx(unsigned mbar, unsigned bytes) {
    asm volatile("mbarrier.arrive.expect_tx.shared.b64 _, [%0], %1;"
                 :: "r"(mbar), "r"(bytes) : "memory");
}
__device__ __forceinline__ void mbar_arrive_local(unsigned mbar) {
    asm volatile("mbarrier.arrive.shared.b64 _, [%0];" :: "r"(mbar) : "memory");
}
__device__ __forceinline__ void mbar_wait(unsigned mbar, unsigned phase) {
    asm volatile(
        "{\n\t"
        ".reg .pred P;\n\t"
        "LW%=:\n\t"
        "mbarrier.try_wait.parity.acquire.cta.shared::cta.b64 P, [%0], %1, 0x989680;\n\t"
        "@P bra LD%=;\n\t"
        "bra LW%=;\n\t"
        "LD%=:\n\t"
        "}"
        :: "r"(mbar), "r"(phase) : "memory");
}
__device__ __forceinline__ void bulk_g2s(unsigned dst, const void* src,
                                         unsigned bytes, unsigned mbar) {
    asm volatile(
        "cp.async.bulk.shared::cta.global.mbarrier::complete_tx::bytes [%0], [%1], %2, [%3];"
        :: "r"(dst), "l"(src), "r"(bytes), "r"(mbar) : "memory");
}
#define CBAR() asm volatile("bar.sync 1, 256;" ::: "memory")

__global__ void ek_nop() {}

// ---------- merged prep: blocks 0-255 do wprep, 256-767 do Gx GEMM ----------
__global__ void __launch_bounds__(256) ek_prep(const float* __restrict__ W,
                                               const float* __restrict__ x,
                                               const float* __restrict__ Wih,
                                               const float* __restrict__ bias) {
    if (blockIdx.x < 256) {
        int k = blockIdx.x, j = threadIdx.x;
        g_Wt[k * 256 + j] = make_float4(W[k * G4 + j], W[k * G4 + 256 + j],
                                        W[k * G4 + 512 + j], W[k * G4 + 768 + j]);
        return;
    }
    __shared__ float As[32][65];
    __shared__ float Bs[32][64];
    const int bx = blockIdx.x - 256;
    const int tid = threadIdx.x;
    const int row0 = (bx >> 4) * 64, col0 = (bx & 15) * 64;
    const int ty = tid >> 4, tx = tid & 15;
    float acc[4][4] = {};
    for (int kb = 0; kb < 256; kb += 32) {
        #pragma unroll
        for (int l = 0; l < 8; l++) {
            int e = l * 256 + tid, r = e >> 5, k = e & 31;
            As[k][r] = x[(size_t)(row0 + r) * 256 + kb + k];
        }
        #pragma unroll
        for (int l = 0; l < 8; l++) {
            int e = l * 256 + tid, k = e >> 6, c = e & 63;
            Bs[k][c] = Wih[(size_t)(kb + k) * G4 + col0 + c];
        }
        __syncthreads();
        #pragma unroll
        for (int k = 0; k < 32; k++) {
            float av[4], bv[4];
            #pragma unroll
            for (int i = 0; i < 4; i++) av[i] = As[k][ty * 4 + i];
            #pragma unroll
            for (int j = 0; j < 4; j++) bv[j] = Bs[k][tx * 4 + j];
            #pragma unroll
            for (int i = 0; i < 4; i++)
                #pragma unroll
                for (int j = 0; j < 4; j++) acc[i][j] += av[i] * bv[j];
        }
        __syncthreads();
    }
    #pragma unroll
    for (int i = 0; i < 4; i++)
        #pragma unroll
        for (int j = 0; j < 4; j++)
            g_Gx[(size_t)(row0 + ty * 4 + i) * G4 + col0 + tx * 4 + j] =
                acc[i][j] + bias[col0 + tx * 4 + j];
}

// ---------- LSTM recurrence (R14, unchanged) ----------
__global__ void __launch_bounds__(NTHR, 1)
ek_lstm(const float* __restrict__ st0,
        const float* __restrict__ eps_h,
        const float* __restrict__ eps_c,
        const float* __restrict__ qp,
        const float* __restrict__ ep) {
    extern __shared__ char smd[];
    ulonglong2* hsd = (ulonglong2*)(smd + ND * TILEB);
    ull*        mbf = (ull*)(smd + ND * TILEB + 16384);
    ull*        mbc = (ull*)(smd + ND * TILEB + 16384 + 64);

    const int jt = threadIdx.x;
    const int b  = blockIdx.x >> 2;
    const int m0 = (blockIdx.x & 3) * 8;
    const unsigned fb0 = smem_u32(mbf);
    const unsigned cb0 = smem_u32(mbc);
    const unsigned ws0 = smem_u32(smd);

    if (jt == 0) {
        #pragma unroll
        for (int d = 0; d < ND; d++) {
            mbar_init(fb0 + d * 8, 1);
            mbar_init(cb0 + d * 8, 8);
        }
    }
    __syncthreads();

    if (jt >= 256) {
        if (jt == 256) {
            #pragma unroll
            for (int d = 0; d < ND; d++) {
                mbar_expect_tx(fb0 + d * 8, TILEB);
                bulk_g2s(ws0 + d * TILEB, (const char*)g_Wt + (size_t)d * TILEB,
                         TILEB, fb0 + d * 8);
            }
            for (unsigned g = 0; g + ND < NT_TOT; g++) {
                const unsigned s  = g % ND;
                const unsigned ph = (g / ND) & 1;
                mbar_wait(cb0 + s * 8, ph);
                unsigned src_tile = (g + ND) % NT_STEP;
                mbar_expect_tx(fb0 + s * 8, TILEB);
                bulk_g2s(ws0 + s * TILEB,
                         (const char*)g_Wt + (size_t)src_tile * TILEB,
                         TILEB, fb0 + s * 8);
            }
        }
    } else {
        const bool lead = ((jt & 31) == 0);
        const float* gxb = g_Gx + ((size_t)b * SEQN) * G4 + jt;
        float c[8];
        float gxv[4];
        #pragma unroll
        for (int gg = 0; gg < 4; gg++) gxv[gg] = gxb[gg * 256];
        {
            const float* srow = st0 + ((size_t)b * NHID + jt) * 64;
            float h0[8];
            #pragma unroll
            for (int i = 0; i < 8; i++) { h0[i] = srow[m0 + i]; c[i] = srow[32 + m0 + i]; }
            #pragma unroll
            for (int p = 0; p < 2; p++) {
                ulonglong2 v;
                v.x = pk2(h0[4 * p], h0[4 * p + 1]);
                v.y = pk2(h0[4 * p + 2], h0[4 * p + 3]);
                hsd[(0 * 256 + jt) * 2 + p] = v;
            }
        }
        CBAR();

        unsigned g = 0;
        for (int t = 0; t < SEQN; t++) {
            const int cb = t & 1, nb = cb ^ 1;
            ull acc[4][4];
            #pragma unroll
            for (int gg = 0; gg < 4; gg++) {
                ull gp = pk2(gxv[gg], gxv[gg]);
                #pragma unroll
                for (int p = 0; p < 4; p++) acc[p][gg] = gp;
            }
            for (int tile = 0; tile < NT_STEP; tile++, g++) {
                const unsigned s  = g % ND;
                const unsigned ph = (g / ND) & 1;
                mbar_wait(fb0 + s * 8, ph);
                const float4* wt = (const float4*)(smd + (size_t)s * TILEB) + jt;
                const ulonglong2* hp = hsd + ((size_t)cb * 256 + tile * TK) * 2;
                #pragma unroll
                for (int kk = 0; kk < TK; kk++) {
                    float4 w = wt[kk * 256];
                    ulonglong2 h01 = hp[kk * 2 + 0];
                    ulonglong2 h23 = hp[kk * 2 + 1];
                    ull wp0 = pk2(w.x, w.x), wp1 = pk2(w.y, w.y);
                    ull wp2 = pk2(w.z, w.z), wp3 = pk2(w.w, w.w);
                    fma2(acc[0][0], h01.x, wp0); fma2(acc[0][1], h01.x, wp1);
                    fma2(acc[0][2], h01.x, wp2); fma2(acc[0][3], h01.x, wp3);
                    fma2(acc[1][0], h01.y, wp0); fma2(acc[1][1], h01.y, wp1);
                    fma2(acc[1][2], h01.y, wp2); fma2(acc[1][3], h01.y, wp3);
                    fma2(acc[2][0], h23.x, wp0); fma2(acc[2][1], h23.x, wp1);
                    fma2(acc[2][2], h23.x, wp2); fma2(acc[2][3], h23.x, wp3);
                    fma2(acc[3][0], h23.y, wp0); fma2(acc[3][1], h23.y, wp1);
                    fma2(acc[3][2], h23.y, wp2); fma2(acc[3][3], h23.y, wp3);
                }
                if (lead) mbar_arrive_local(cb0 + s * 8);
            }
            if (t + 1 < SEQN) {
                const float* gxn = gxb + (size_t)(t + 1) * G4;
                #pragma unroll
                for (int gg = 0; gg < 4; gg++) gxv[gg] = gxn[gg * 256];
            }
            {
                ulonglong2 v0, v1;
                {
                    float2 gi = upk2(acc[0][0]), gf = upk2(acc[0][1]);
                    float2 gg2 = upk2(acc[0][2]), go = upk2(acc[0][3]);
                    float c0 = siga(gf.x) * c[0] + siga(gi.x) * tanha(gg2.x);
                    float c1 = siga(gf.y) * c[1] + siga(gi.y) * tanha(gg2.y);
                    c[0] = c0; c[1] = c1;
                    v0.x = pk2(siga(go.x) * tanha(c0), siga(go.y) * tanha(c1));
                }
                {
                    float2 gi = upk2(acc[1][0]), gf = upk2(acc[1][1]);
                    float2 gg2 = upk2(acc[1][2]), go = upk2(acc[1][3]);
                    float c0 = siga(gf.x) * c[2] + siga(gi.x) * tanha(gg2.x);
                    float c1 = siga(gf.y) * c[3] + siga(gi.y) * tanha(gg2.y);
                    c[2] = c0; c[3] = c1;
                    v0.y = pk2(siga(go.x) * tanha(c0), siga(go.y) * tanha(c1));
                }
                {
                    float2 gi = upk2(acc[2][0]), gf = upk2(acc[2][1]);
                    float2 gg2 = upk2(acc[2][2]), go = upk2(acc[2][3]);
                    float c0 = siga(gf.x) * c[4] + siga(gi.x) * tanha(gg2.x);
                    float c1 = siga(gf.y) * c[5] + siga(gi.y) * tanha(gg2.y);
                    c[4] = c0; c[5] = c1;
                    v1.x = pk2(siga(go.x) * tanha(c0), siga(go.y) * tanha(c1));
                }
                {
                    float2 gi = upk2(acc[3][0]), gf = upk2(acc[3][1]);
                    float2 gg2 = upk2(acc[3][2]), go = upk2(acc[3][3]);
                    float c0 = siga(gf.x) * c[6] + siga(gi.x) * tanha(gg2.x);
                    float c1 = siga(gf.y) * c[7] + siga(gi.y) * tanha(gg2.y);
                    c[6] = c0; c[7] = c1;
                    v1.y = pk2(siga(go.x) * tanha(c0), siga(go.y) * tanha(c1));
                }
                hsd[(nb * 256 + jt) * 2 + 0] = v0;
                hsd[(nb * 256 + jt) * 2 + 1] = v1;
            }
            CBAR();
        }

        const float nq = fabsf(qp[0]), ne = fabsf(ep[0]);
        float* orow = g_state_f + ((size_t)b * NHID + jt) * 64;
        ulonglong2 f0 = hsd[(0 * 256 + jt) * 2 + 0];
        ulonglong2 f1 = hsd[(0 * 256 + jt) * 2 + 1];
        float2 hf[4] = { upk2(f0.x), upk2(f0.y), upk2(f1.x), upk2(f1.y) };
        #pragma unroll
        for (int p = 0; p < 4; p++) {
            int ma = m0 + 2 * p, mb2 = ma + 1;
            orow[ma]  = hf[p].x + nq * eps_h[((size_t)ma * BSN + b) * NHID + jt];
            orow[mb2] = hf[p].y + nq * eps_h[((size_t)mb2 * BSN + b) * NHID + jt];
            orow[32 + ma]  = c[2 * p]     + ne * eps_c[((size_t)ma * BSN + b) * NHID + jt];
            orow[32 + mb2] = c[2 * p + 1] + ne * eps_c[((size_t)mb2 * BSN + b) * NHID + jt];
        }
    }
}

// ---------- warp-resident Cholesky (warp 0, __syncwarp only) ----------
// Square-of-triangle update: writes above-diagonal garbage; never read.
__device__ __forceinline__ void chol64_warp(float* A, int lane) {
    for (int k = 0; k < 64; k++) {
        if (lane == 0) A[k * 65 + k] = sqrtf(A[k * 65 + k]);
        __syncwarp();
        float linv = __fdividef(1.0f, A[k * 65 + k]);
        for (int r = k + 1 + lane; r < 64; r += 32) A[r * 65 + k] *= linv;
        __syncwarp();
        for (int r = k + 1 + (lane >> 2); r < 64; r += 8) {
            float ark = A[r * 65 + k];
            for (int c2 = k + 1 + (lane & 3); c2 <= r; c2 += 4)
                A[r * 65 + c2] -= ark * A[c2 * 65 + k];
        }
        __syncwarp();
    }
}

// ---------- fused tail: warp-level factor/solve, minimal block barriers ----------
__global__ void __launch_bounds__(256) ek_tail(const float* __restrict__ Wh,
                                               const float* __restrict__ bh,
                                               const float* __restrict__ y,
                                               const float* __restrict__ rp,
                                               float* __restrict__ out_mu,
                                               float* __restrict__ out_sig,
                                               float* __restrict__ out_state) {
    extern __shared__ float sm[];
    float* ss      = sm;                 // 16384
    float* whs     = ss + 16384;         // 16384
    float* hsm     = whs + 16384;        // 4160
    float* Psm     = hsm + 4160;         // 4160
    float* X       = Psm + 4160;         // 4160 (pitch 65)
    float* mean_s  = X + 4160;           // 64
    float* rowmean = mean_s + 64;        // 256
    float* vv      = rowmean + 256;      // 64
    float* iv      = vv + 64;            // 64
    float* dinv    = iv + 64;            // 64

    const int b = blockIdx.x, tid = threadIdx.x;
    const int i = tid & 63, mg = tid >> 6;
    const float rr = rp[0] * rp[0];

    for (int idx = tid; idx < 16384; idx += 256) {
        ss[idx]  = g_state_f[(size_t)b * 16384 + idx];
        whs[idx] = Wh[idx];
    }
    __syncthreads();

    {
        float s = 0.f;
        #pragma unroll 8
        for (int ii = 0; ii < 64; ii++) s += ss[tid * 64 + ((ii + tid) & 63)];
        rowmean[tid] = s * (1.0f / 64.0f);
    }

    // ---- hxi_f ----
    {
        float acc[16] = {};
        #pragma unroll 4
        for (int n = 0; n < 256; n++) {
            float sv = ss[n * 64 + i];
            #pragma unroll
            for (int mi = 0; mi < 16; mi++)
                acc[mi] += whs[(mg * 16 + mi) * 256 + n] * sv;
        }
        #pragma unroll
        for (int mi = 0; mi < 16; mi++) {
            int m = mg * 16 + mi;
            hsm[m * 65 + i] = acc[mi] + bh[m];
        }
    }
    __syncthreads();
    for (int idx = tid; idx < 4096; idx += 256) {
        int m = idx >> 6, k = idx & 63;
        X[m * 65 + k] = y[b * 64 + m] - hsm[m * 65 + k];
    }
    if (tid < 64) {
        float s = 0.f;
        for (int k = 0; k < 64; k++) s += hsm[tid * 65 + k];
        mean_s[tid] = s * (1.0f / 64.0f);
    }
    __syncthreads();
    for (int idx = tid; idx < 4096; idx += 256) {
        int m = idx >> 6, k = idx & 63;
        hsm[m * 65 + k] -= mean_s[m];
    }
    __syncthreads();
    // ---- P_f ----
    {
        const int m2 = i;
        for (int mi = 0; mi < 16; mi++) {
            int m = mg * 16 + mi;
            float s = 0.f;
            #pragma unroll 8
            for (int k = 0; k < 64; k++) s += hsm[m * 65 + k] * hsm[m2 * 65 + k];
            float v = s * (1.0f / 63.0f);
            if (m == m2) v += rr;
            Psm[m * 65 + m2] = v;
        }
    }
    __syncthreads();
    // ---- chol (warp 0) ----
    if (tid < 32) {
        chol64_warp(Psm, tid);
        dinv[tid]      = __fdividef(1.0f, Psm[tid * 65 + tid]);
        dinv[tid + 32] = __fdividef(1.0f, Psm[(tid + 32) * 65 + tid + 32]);
    }
    __syncthreads();
    // ---- 64-RHS trisolves: warp w owns columns 8w..8w+7, __syncwarp only ----
    {
        const int w = tid >> 5, lane = tid & 31;
        const int col = (w << 3) + (lane & 7), g = lane >> 3;
        // forward: L Y = B
        for (int k = 0; k < 64; k++) {
            if (g == 0) X[k * 65 + col] *= dinv[k];
            __syncwarp();
            float xk = X[k * 65 + col];
            for (int r = k + 1 + g; r < 64; r += 4)
                X[r * 65 + col] -= Psm[r * 65 + k] * xk;
            __syncwarp();
        }
        // backward: L^T X = Y
        for (int k = 63; k >= 0; k--) {
            if (g == 0) X[k * 65 + col] *= dinv[k];
            __syncwarp();
            float xk = X[k * 65 + col];
            for (int r = g; r < k; r += 4)
                X[r * 65 + col] -= Psm[k * 65 + r] * xk;
            __syncwarp();
        }
    }
    __syncthreads();
    // ---- M1 = HA^T X / 63 (into X) ----
    {
        float m1r[16];
        for (int ji = 0; ji < 16; ji++) {
            int j = mg * 16 + ji;
            float s = 0.f;
            #pragma unroll 8
            for (int m = 0; m < 64; m++) s += hsm[m * 65 + j] * X[m * 65 + i];
            m1r[ji] = s * (1.0f / 63.0f);
        }
        __syncthreads();
        for (int ji = 0; ji < 16; ji++) X[(mg * 16 + ji) * 65 + i] = m1r[ji];
    }
    __syncthreads();
    // ---- state update ----
    for (int chunk = 0; chunk < 4; chunk++) {
        int n0 = chunk * 64;
        float accv[16];
        #pragma unroll
        for (int l = 0; l < 16; l++) {
            int n = n0 + mg * 16 + l;
            float mn = rowmean[n];
            float a = 0.f;
            #pragma unroll 8
            for (int j = 0; j < 64; j++) a += (ss[n * 64 + j] - mn) * X[j * 65 + i];
            accv[l] = ss[n * 64 + i] + a;
        }
        __syncthreads();
        #pragma unroll
        for (int l = 0; l < 16; l++) {
            int n = n0 + mg * 16 + l;
            ss[n * 64 + i] = accv[l];
            out_state[(size_t)b * 16384 + n * 64 + i] = accv[l];
        }
        __syncthreads();
    }
    // ---- hxi_a, mu, P_a ----
    {
        float acc[16] = {};
        #pragma unroll 4
        for (int n = 0; n < 256; n++) {
            float sv = ss[n * 64 + i];
            #pragma unroll
            for (int mi = 0; mi < 16; mi++)
                acc[mi] += whs[(mg * 16 + mi) * 256 + n] * sv;
        }
        #pragma unroll
        for (int mi = 0; mi < 16; mi++) {
            int m = mg * 16 + mi;
            hsm[m * 65 + i] = acc[mi] + bh[m];
        }
    }
    __syncthreads();
    if (tid < 64) {
        float s = 0.f;
        for (int k = 0; k < 64; k++) s += hsm[tid * 65 + k];
        s *= (1.0f / 64.0f);
        mean_s[tid] = s;
        out_mu[b * 64 + tid] = s;
        float d = y[b * 64 + tid] - s;
        vv[tid] = d; iv[tid] = d;
    }
    __syncthreads();
    for (int idx = tid; idx < 4096; idx += 256) {
        int m = idx >> 6, k = idx & 63;
        hsm[m * 65 + k] -= mean_s[m];
    }
    __syncthreads();
    {
        const int m2 = i;
        for (int mi = 0; mi < 16; mi++) {
            int m = mg * 16 + mi;
            float s = 0.f;
            #pragma unroll 8
            for (int k = 0; k < 64; k++) s += hsm[m * 65 + k] * hsm[m2 * 65 + k];
            float v = s * (1.0f / 63.0f);
            if (m == m2) v += rr;
            Psm[m * 65 + m2] = v;
            out_sig[(size_t)b * 4096 + m * 64 + m2] = v;
        }
    }
    __syncthreads();
    if (tid < 64) Psm[tid * 65 + tid] += 1e-6f;
    __syncthreads();
    // ---- loglik: warp 0 does chol + vector solves + reduction ----
    if (tid < 32) {
        const int lane = tid;
        chol64_warp(Psm, lane);
        dinv[lane]      = __fdividef(1.0f, Psm[lane * 65 + lane]);
        dinv[lane + 32] = __fdividef(1.0f, Psm[(lane + 32) * 65 + lane + 32]);
        __syncwarp();
        for (int k = 0; k < 64; k++) {
            if (lane == 0) vv[k] *= dinv[k];
            __syncwarp();
            float vk = vv[k];
            for (int r = k + 1 + lane; r < 64; r += 32) vv[r] -= Psm[r * 65 + k] * vk;
            __syncwarp();
        }
        for (int k = 63; k >= 0; k--) {
            if (lane == 0) vv[k] *= dinv[k];
            __syncwarp();
            float vk = vv[k];
            for (int r = lane; r < k; r += 32) vv[r] -= Psm[k * 65 + r] * vk;
            __syncwarp();
        }
        if (lane == 0) {
            float quad = 0.f, ld = 0.f;
            for (int m = 0; m < 64; m++) { quad += iv[m] * vv[m]; ld += __logf(Psm[m * 65 + m]); }
            g_part[b * 2] = quad;
            g_part[b * 2 + 1] = 2.f * ld;
        }
    }
}

__global__ void ek_reduce(float* __restrict__ out) {
    int t = threadIdx.x;
    float q = g_part[t * 2], ld = g_part[t * 2 + 1];
    float l = -0.5f * ld - 0.5f * q;
    #pragma unroll
    for (int s = 16; s; s >>= 1) {
        l += __shfl_xor_sync(0xffffffffu, l, s);
        q += __shfl_xor_sync(0xffffffffu, q, s);
    }
    if (t == 0) { out[0] = l; out[1] = q * (1.0f / 32.0f); }
}

extern "C" void kernel_launch(void* const* d_in, const int* in_sizes, int n_in,
                              void* d_out, int out_size) {
    const float* x    = (const float*)d_in[0];
    const float* y    = (const float*)d_in[1];
    const float* st0  = (const float*)d_in[2];
    const float* Wih  = (const float*)d_in[3];
    const float* Whh  = (const float*)d_in[4];
    const float* bias = (const float*)d_in[5];
    const float* Wh   = (const float*)d_in[6];
    const float* bh   = (const float*)d_in[7];
    const float* q    = (const float*)d_in[8];
    const float* e    = (const float*)d_in[9];
    const float* r    = (const float*)d_in[10];
    const float* eph  = (const float*)d_in[11];
    const float* epc  = (const float*)d_in[12];

    float* out       = (float*)d_out;
    float* out_mu    = out;
    float* out_sig   = out + 2048;
    float* out_state = out + 2048 + 131072;
    float* out_l     = out + 2048 + 131072 + 524288;

    const int SMEM_LSTM = ND * TILEB + 16384 + 256;
    const int SMEM_TAIL = (16384 + 16384 + 4160 + 4160 + 4160 + 64 + 256 + 64 + 64 + 64) * 4;
    static int smem_set = 0;
    if (!smem_set) {
        cudaFuncSetAttribute(ek_lstm, cudaFuncAttributeMaxDynamicSharedMemorySize,
                             SMEM_LSTM);
        cudaFuncSetAttribute(ek_tail, cudaFuncAttributeMaxDynamicSharedMemorySize,
                             SMEM_TAIL);
        smem_set = 1;
    }

    ek_prep<<<768, 256>>>(Whh, x, Wih, bias);
    ek_lstm<<<128, NTHR, SMEM_LSTM>>>(st0, eph, epc, q, e);
    ek_nop<<<1, 32>>>();   // keeps ek_tail in the ncu 4th-launch capture slot
    ek_tail<<<32, 256, SMEM_TAIL>>>(Wh, bh, y, r, out_mu, out_sig, out_state);
    ek_reduce<<<1, 32>>>(out_l);
    (void)in_sizes; (void)n_in; (void)out_size;
}

// round 17
// speedup vs baseline: 1.1204x; 1.1204x over previous
#include <cuda_runtime.h>
#include <math.h>

#define SEQN 64
#define BSN  32
#define NHID 256
#define G4   1024

#define TK        16
#define ND        3
#define TILEB     (TK * G4 * 4)
#define NT_STEP   (NHID / TK)
#define NT_TOT    (SEQN * NT_STEP)
#define NTHR      288

__device__ float  g_Gx[BSN * SEQN * G4];
__device__ float4 g_Wt[256 * 256];
__device__ float  g_state_f[BSN * NHID * 64];
__device__ float  g_part[BSN * 2];

typedef unsigned long long ull;

__device__ __forceinline__ ull pk2(float a, float b) {
    ull r;
    asm("mov.b64 %0, {%1, %2};" : "=l"(r) : "f"(a), "f"(b));
    return r;
}
__device__ __forceinline__ float2 upk2(ull v) {
    float2 r;
    asm("mov.b64 {%0, %1}, %2;" : "=f"(r.x), "=f"(r.y) : "l"(v));
    return r;
}
__device__ __forceinline__ void fma2(ull& acc, ull a, ull b) {
    asm("fma.rn.f32x2 %0, %1, %2, %0;" : "+l"(acc) : "l"(a), "l"(b));
}
__device__ __forceinline__ float tanha(float x) {
    float r;
    asm("tanh.approx.f32 %0, %1;" : "=f"(r) : "f"(x));
    return r;
}
__device__ __forceinline__ float siga(float x) {
    return fmaf(0.5f, tanha(0.5f * x), 0.5f);
}

__device__ __forceinline__ unsigned smem_u32(const void* p) {
    unsigned a;
    asm("{ .reg .u64 t; cvta.to.shared.u64 t, %1; cvt.u32.u64 %0, t; }"
        : "=r"(a) : "l"(p));
    return a;
}
__device__ __forceinline__ void mbar_init(unsigned mbar, unsigned cnt) {
    asm volatile("mbarrier.init.shared.b64 [%0], %1;" :: "r"(mbar), "r"(cnt) : "memory");
}
__device__ __forceinline__ void mbar_expect_tx(unsigned mbar, unsigned bytes) {
    asm volatile("mbarrier.arrive.expect_tx.shared.b64 _, [%0], %1;"
                 :: "r"(mbar), "r"(bytes) : "memory");
}
__device__ __forceinline__ void mbar_arrive_local(unsigned mbar) {
    asm volatile("mbarrier.arrive.shared.b64 _, [%0];" :: "r"(mbar) : "memory");
}
__device__ __forceinline__ void mbar_wait(unsigned mbar, unsigned phase) {
    asm volatile(
        "{\n\t"
        ".reg .pred P;\n\t"
        "LW%=:\n\t"
        "mbarrier.try_wait.parity.acquire.cta.shared::cta.b64 P, [%0], %1, 0x989680;\n\t"
        "@P bra LD%=;\n\t"
        "bra LW%=;\n\t"
        "LD%=:\n\t"
        "}"
        :: "r"(mbar), "r"(phase) : "memory");
}
__device__ __forceinline__ void bulk_g2s(unsigned dst, const void* src,
                                         unsigned bytes, unsigned mbar) {
    asm volatile(
        "cp.async.bulk.shared::cta.global.mbarrier::complete_tx::bytes [%0], [%1], %2, [%3];"
        :: "r"(dst), "l"(src), "r"(bytes), "r"(mbar) : "memory");
}
#define CBAR() asm volatile("bar.sync 1, 256;" ::: "memory")

__global__ void ek_nop() {}

// ---------- merged prep: blocks 0-255 do wprep, 256-767 do Gx GEMM ----------
__global__ void __launch_bounds__(256) ek_prep(const float* __restrict__ W,
                                               const float* __restrict__ x,
                                               const float* __restrict__ Wih,
                                               const float* __restrict__ bias) {
    if (blockIdx.x < 256) {
        int k = blockIdx.x, j = threadIdx.x;
        g_Wt[k * 256 + j] = make_float4(W[k * G4 + j], W[k * G4 + 256 + j],
                                        W[k * G4 + 512 + j], W[k * G4 + 768 + j]);
        return;
    }
    __shared__ float As[32][65];
    __shared__ float Bs[32][64];
    const int bx = blockIdx.x - 256;
    const int tid = threadIdx.x;
    const int row0 = (bx >> 4) * 64, col0 = (bx & 15) * 64;
    const int ty = tid >> 4, tx = tid & 15;
    float acc[4][4] = {};
    for (int kb = 0; kb < 256; kb += 32) {
        #pragma unroll
        for (int l = 0; l < 8; l++) {
            int e = l * 256 + tid, r = e >> 5, k = e & 31;
            As[k][r] = x[(size_t)(row0 + r) * 256 + kb + k];
        }
        #pragma unroll
        for (int l = 0; l < 8; l++) {
            int e = l * 256 + tid, k = e >> 6, c = e & 63;
            Bs[k][c] = Wih[(size_t)(kb + k) * G4 + col0 + c];
        }
        __syncthreads();
        #pragma unroll
        for (int k = 0; k < 32; k++) {
            float av[4], bv[4];
            #pragma unroll
            for (int i = 0; i < 4; i++) av[i] = As[k][ty * 4 + i];
            #pragma unroll
            for (int j = 0; j < 4; j++) bv[j] = Bs[k][tx * 4 + j];
            #pragma unroll
            for (int i = 0; i < 4; i++)
                #pragma unroll
                for (int j = 0; j < 4; j++) acc[i][j] += av[i] * bv[j];
        }
        __syncthreads();
    }
    #pragma unroll
    for (int i = 0; i < 4; i++)
        #pragma unroll
        for (int j = 0; j < 4; j++)
            g_Gx[(size_t)(row0 + ty * 4 + i) * G4 + col0 + tx * 4 + j] =
                acc[i][j] + bias[col0 + tx * 4 + j];
}

// ---------- LSTM recurrence (R14, unchanged) ----------
__global__ void __launch_bounds__(NTHR, 1)
ek_lstm(const float* __restrict__ st0,
        const float* __restrict__ eps_h,
        const float* __restrict__ eps_c,
        const float* __restrict__ qp,
        const float* __restrict__ ep) {
    extern __shared__ char smd[];
    ulonglong2* hsd = (ulonglong2*)(smd + ND * TILEB);
    ull*        mbf = (ull*)(smd + ND * TILEB + 16384);
    ull*        mbc = (ull*)(smd + ND * TILEB + 16384 + 64);

    const int jt = threadIdx.x;
    const int b  = blockIdx.x >> 2;
    const int m0 = (blockIdx.x & 3) * 8;
    const unsigned fb0 = smem_u32(mbf);
    const unsigned cb0 = smem_u32(mbc);
    const unsigned ws0 = smem_u32(smd);

    if (jt == 0) {
        #pragma unroll
        for (int d = 0; d < ND; d++) {
            mbar_init(fb0 + d * 8, 1);
            mbar_init(cb0 + d * 8, 8);
        }
    }
    __syncthreads();

    if (jt >= 256) {
        if (jt == 256) {
            #pragma unroll
            for (int d = 0; d < ND; d++) {
                mbar_expect_tx(fb0 + d * 8, TILEB);
                bulk_g2s(ws0 + d * TILEB, (const char*)g_Wt + (size_t)d * TILEB,
                         TILEB, fb0 + d * 8);
            }
            for (unsigned g = 0; g + ND < NT_TOT; g++) {
                const unsigned s  = g % ND;
                const unsigned ph = (g / ND) & 1;
                mbar_wait(cb0 + s * 8, ph);
                unsigned src_tile = (g + ND) % NT_STEP;
                mbar_expect_tx(fb0 + s * 8, TILEB);
                bulk_g2s(ws0 + s * TILEB,
                         (const char*)g_Wt + (size_t)src_tile * TILEB,
                         TILEB, fb0 + s * 8);
            }
        }
    } else {
        const bool lead = ((jt & 31) == 0);
        const float* gxb = g_Gx + ((size_t)b * SEQN) * G4 + jt;
        float c[8];
        float gxv[4];
        #pragma unroll
        for (int gg = 0; gg < 4; gg++) gxv[gg] = gxb[gg * 256];
        {
            const float* srow = st0 + ((size_t)b * NHID + jt) * 64;
            float h0[8];
            #pragma unroll
            for (int i = 0; i < 8; i++) { h0[i] = srow[m0 + i]; c[i] = srow[32 + m0 + i]; }
            #pragma unroll
            for (int p = 0; p < 2; p++) {
                ulonglong2 v;
                v.x = pk2(h0[4 * p], h0[4 * p + 1]);
                v.y = pk2(h0[4 * p + 2], h0[4 * p + 3]);
                hsd[(0 * 256 + jt) * 2 + p] = v;
            }
        }
        CBAR();

        unsigned g = 0;
        for (int t = 0; t < SEQN; t++) {
            const int cb = t & 1, nb = cb ^ 1;
            ull acc[4][4];
            #pragma unroll
            for (int gg = 0; gg < 4; gg++) {
                ull gp = pk2(gxv[gg], gxv[gg]);
                #pragma unroll
                for (int p = 0; p < 4; p++) acc[p][gg] = gp;
            }
            for (int tile = 0; tile < NT_STEP; tile++, g++) {
                const unsigned s  = g % ND;
                const unsigned ph = (g / ND) & 1;
                mbar_wait(fb0 + s * 8, ph);
                const float4* wt = (const float4*)(smd + (size_t)s * TILEB) + jt;
                const ulonglong2* hp = hsd + ((size_t)cb * 256 + tile * TK) * 2;
                #pragma unroll
                for (int kk = 0; kk < TK; kk++) {
                    float4 w = wt[kk * 256];
                    ulonglong2 h01 = hp[kk * 2 + 0];
                    ulonglong2 h23 = hp[kk * 2 + 1];
                    ull wp0 = pk2(w.x, w.x), wp1 = pk2(w.y, w.y);
                    ull wp2 = pk2(w.z, w.z), wp3 = pk2(w.w, w.w);
                    fma2(acc[0][0], h01.x, wp0); fma2(acc[0][1], h01.x, wp1);
                    fma2(acc[0][2], h01.x, wp2); fma2(acc[0][3], h01.x, wp3);
                    fma2(acc[1][0], h01.y, wp0); fma2(acc[1][1], h01.y, wp1);
                    fma2(acc[1][2], h01.y, wp2); fma2(acc[1][3], h01.y, wp3);
                    fma2(acc[2][0], h23.x, wp0); fma2(acc[2][1], h23.x, wp1);
                    fma2(acc[2][2], h23.x, wp2); fma2(acc[2][3], h23.x, wp3);
                    fma2(acc[3][0], h23.y, wp0); fma2(acc[3][1], h23.y, wp1);
                    fma2(acc[3][2], h23.y, wp2); fma2(acc[3][3], h23.y, wp3);
                }
                if (lead) mbar_arrive_local(cb0 + s * 8);
            }
            if (t + 1 < SEQN) {
                const float* gxn = gxb + (size_t)(t + 1) * G4;
                #pragma unroll
                for (int gg = 0; gg < 4; gg++) gxv[gg] = gxn[gg * 256];
            }
            {
                ulonglong2 v0, v1;
                {
                    float2 gi = upk2(acc[0][0]), gf = upk2(acc[0][1]);
                    float2 gg2 = upk2(acc[0][2]), go = upk2(acc[0][3]);
                    float c0 = siga(gf.x) * c[0] + siga(gi.x) * tanha(gg2.x);
                    float c1 = siga(gf.y) * c[1] + siga(gi.y) * tanha(gg2.y);
                    c[0] = c0; c[1] = c1;
                    v0.x = pk2(siga(go.x) * tanha(c0), siga(go.y) * tanha(c1));
                }
                {
                    float2 gi = upk2(acc[1][0]), gf = upk2(acc[1][1]);
                    float2 gg2 = upk2(acc[1][2]), go = upk2(acc[1][3]);
                    float c0 = siga(gf.x) * c[2] + siga(gi.x) * tanha(gg2.x);
                    float c1 = siga(gf.y) * c[3] + siga(gi.y) * tanha(gg2.y);
                    c[2] = c0; c[3] = c1;
                    v0.y = pk2(siga(go.x) * tanha(c0), siga(go.y) * tanha(c1));
                }
                {
                    float2 gi = upk2(acc[2][0]), gf = upk2(acc[2][1]);
                    float2 gg2 = upk2(acc[2][2]), go = upk2(acc[2][3]);
                    float c0 = siga(gf.x) * c[4] + siga(gi.x) * tanha(gg2.x);
                    float c1 = siga(gf.y) * c[5] + siga(gi.y) * tanha(gg2.y);
                    c[4] = c0; c[5] = c1;
                    v1.x = pk2(siga(go.x) * tanha(c0), siga(go.y) * tanha(c1));
                }
                {
                    float2 gi = upk2(acc[3][0]), gf = upk2(acc[3][1]);
                    float2 gg2 = upk2(acc[3][2]), go = upk2(acc[3][3]);
                    float c0 = siga(gf.x) * c[6] + siga(gi.x) * tanha(gg2.x);
                    float c1 = siga(gf.y) * c[7] + siga(gi.y) * tanha(gg2.y);
                    c[6] = c0; c[7] = c1;
                    v1.y = pk2(siga(go.x) * tanha(c0), siga(go.y) * tanha(c1));
                }
                hsd[(nb * 256 + jt) * 2 + 0] = v0;
                hsd[(nb * 256 + jt) * 2 + 1] = v1;
            }
            CBAR();
        }

        const float nq = fabsf(qp[0]), ne = fabsf(ep[0]);
        float* orow = g_state_f + ((size_t)b * NHID + jt) * 64;
        ulonglong2 f0 = hsd[(0 * 256 + jt) * 2 + 0];
        ulonglong2 f1 = hsd[(0 * 256 + jt) * 2 + 1];
        float2 hf[4] = { upk2(f0.x), upk2(f0.y), upk2(f1.x), upk2(f1.y) };
        #pragma unroll
        for (int p = 0; p < 4; p++) {
            int ma = m0 + 2 * p, mb2 = ma + 1;
            orow[ma]  = hf[p].x + nq * eps_h[((size_t)ma * BSN + b) * NHID + jt];
            orow[mb2] = hf[p].y + nq * eps_h[((size_t)mb2 * BSN + b) * NHID + jt];
            orow[32 + ma]  = c[2 * p]     + ne * eps_c[((size_t)ma * BSN + b) * NHID + jt];
            orow[32 + mb2] = c[2 * p + 1] + ne * eps_c[((size_t)mb2 * BSN + b) * NHID + jt];
        }
    }
}

// ---------- blocked (rank-8) Cholesky: 24 block barriers, all threads active ----------
__device__ void chol64_blk(float* A, float* dinv, int tid) {
    for (int kb = 0; kb < 64; kb += 8) {
        // factor 8x8 diag block (thread 0, serial)
        if (tid == 0) {
            for (int k = kb; k < kb + 8; k++) {
                float d = A[k * 65 + k];
                for (int j = kb; j < k; j++) d -= A[k * 65 + j] * A[k * 65 + j];
                d = sqrtf(d);
                A[k * 65 + k] = d;
                float di = __fdividef(1.0f, d);
                dinv[k] = di;
                for (int r = k + 1; r < kb + 8; r++) {
                    float s = A[r * 65 + k];
                    for (int j = kb; j < k; j++) s -= A[r * 65 + j] * A[k * 65 + j];
                    A[r * 65 + k] = s * di;
                }
            }
        }
        __syncthreads();
        // panel solve: rows kb+8..63 against the 8x8 block (parallel over rows)
        for (int r = kb + 8 + tid; r < 64; r += 256) {
            float v[8];
            #pragma unroll
            for (int k = 0; k < 8; k++) v[k] = A[r * 65 + kb + k];
            #pragma unroll
            for (int k = 0; k < 8; k++) {
                float s = v[k];
                for (int j = 0; j < k; j++) s -= v[j] * A[(kb + k) * 65 + kb + j];
                v[k] = s * dinv[kb + k];
            }
            #pragma unroll
            for (int k = 0; k < 8; k++) A[r * 65 + kb + k] = v[k];
        }
        __syncthreads();
        // rank-8 trailing update (parallel)
        int rem = 56 - kb;
        for (int idx = tid; idx < rem * rem; idx += 256) {
            int r = kb + 8 + idx / rem, c2 = kb + 8 + idx % rem;
            if (c2 <= r) {
                float s = 0.f;
                #pragma unroll
                for (int k = 0; k < 8; k++) s += A[r * 65 + kb + k] * A[c2 * 65 + kb + k];
                A[r * 65 + c2] -= s;
            }
        }
        __syncthreads();
    }
}

// ---------- fused tail: blocked factor/solve ----------
__global__ void __launch_bounds__(256) ek_tail(const float* __restrict__ Wh,
                                               const float* __restrict__ bh,
                                               const float* __restrict__ y,
                                               const float* __restrict__ rp,
                                               float* __restrict__ out_mu,
                                               float* __restrict__ out_sig,
                                               float* __restrict__ out_state) {
    extern __shared__ float sm[];
    float* ss      = sm;                 // 16384
    float* whs     = ss + 16384;         // 16384
    float* hsm     = whs + 16384;        // 4160
    float* Psm     = hsm + 4160;         // 4160
    float* X       = Psm + 4160;         // 4096
    float* mean_s  = X + 4096;           // 64
    float* rowmean = mean_s + 64;        // 256
    float* vv      = rowmean + 256;      // 64
    float* iv      = vv + 64;            // 64
    float* dinv    = iv + 64;            // 64

    const int b = blockIdx.x, tid = threadIdx.x;
    const int i = tid & 63, mg = tid >> 6;
    const float rr = rp[0] * rp[0];

    for (int idx = tid; idx < 16384; idx += 256) {
        ss[idx]  = g_state_f[(size_t)b * 16384 + idx];
        whs[idx] = Wh[idx];
    }
    __syncthreads();

    {
        float s = 0.f;
        #pragma unroll 8
        for (int ii = 0; ii < 64; ii++) s += ss[tid * 64 + ((ii + tid) & 63)];
        rowmean[tid] = s * (1.0f / 64.0f);
    }

    // ---- hxi_f ----
    {
        float acc[16] = {};
        #pragma unroll 4
        for (int n = 0; n < 256; n++) {
            float sv = ss[n * 64 + i];
            #pragma unroll
            for (int mi = 0; mi < 16; mi++)
                acc[mi] += whs[(mg * 16 + mi) * 256 + n] * sv;
        }
        #pragma unroll
        for (int mi = 0; mi < 16; mi++) {
            int m = mg * 16 + mi;
            hsm[m * 65 + i] = acc[mi] + bh[m];
        }
    }
    __syncthreads();
    for (int idx = tid; idx < 4096; idx += 256) {
        int m = idx >> 6, k = idx & 63;
        X[m * 64 + k] = y[b * 64 + m] - hsm[m * 65 + k];
    }
    if (tid < 64) {
        float s = 0.f;
        for (int k = 0; k < 64; k++) s += hsm[tid * 65 + k];
        mean_s[tid] = s * (1.0f / 64.0f);
    }
    __syncthreads();
    for (int idx = tid; idx < 4096; idx += 256) {
        int m = idx >> 6, k = idx & 63;
        hsm[m * 65 + k] -= mean_s[m];
    }
    __syncthreads();
    // ---- P_f ----
    {
        const int m2 = i;
        for (int mi = 0; mi < 16; mi++) {
            int m = mg * 16 + mi;
            float s = 0.f;
            #pragma unroll 8
            for (int k = 0; k < 64; k++) s += hsm[m * 65 + k] * hsm[m2 * 65 + k];
            float v = s * (1.0f / 63.0f);
            if (m == m2) v += rr;
            Psm[m * 65 + m2] = v;
        }
    }
    __syncthreads();
    chol64_blk(Psm, dinv, tid);
    // ---- blocked forward solve: L Y = B (8-row blocks) ----
    for (int kb = 0; kb < 64; kb += 8) {
        if (tid < 64) {
            const int c2 = tid;
            float v[8];
            #pragma unroll
            for (int k = 0; k < 8; k++) v[k] = X[(kb + k) * 64 + c2];
            #pragma unroll
            for (int k = 0; k < 8; k++) {
                float s = v[k];
                for (int j = 0; j < k; j++) s -= Psm[(kb + k) * 65 + kb + j] * v[j];
                v[k] = s * dinv[kb + k];
            }
            #pragma unroll
            for (int k = 0; k < 8; k++) X[(kb + k) * 64 + c2] = v[k];
        }
        __syncthreads();
        int rem = 56 - kb;
        for (int idx = tid; idx < rem * 64; idx += 256) {
            int r = kb + 8 + (idx >> 6), c2 = idx & 63;
            float s = 0.f;
            #pragma unroll
            for (int k = 0; k < 8; k++) s += Psm[r * 65 + kb + k] * X[(kb + k) * 64 + c2];
            X[r * 64 + c2] -= s;
        }
        __syncthreads();
    }
    // ---- blocked backward solve: L^T X = Y ----
    for (int kb = 56; kb >= 0; kb -= 8) {
        if (tid < 64) {
            const int c2 = tid;
            float v[8];
            #pragma unroll
            for (int k = 0; k < 8; k++) v[k] = X[(kb + k) * 64 + c2];
            #pragma unroll
            for (int k = 7; k >= 0; k--) {
                float s = v[k];
                for (int j = k + 1; j < 8; j++) s -= Psm[(kb + j) * 65 + kb + k] * v[j];
                v[k] = s * dinv[kb + k];
            }
            #pragma unroll
            for (int k = 0; k < 8; k++) X[(kb + k) * 64 + c2] = v[k];
        }
        __syncthreads();
        for (int idx = tid; idx < kb * 64; idx += 256) {
            int r = idx >> 6, c2 = idx & 63;
            float s = 0.f;
            #pragma unroll
            for (int k = 0; k < 8; k++) s += Psm[(kb + k) * 65 + r] * X[(kb + k) * 64 + c2];
            X[r * 64 + c2] -= s;
        }
        __syncthreads();
    }
    // ---- M1 = HA^T X / 63 (into X) ----
    {
        float m1r[16];
        for (int ji = 0; ji < 16; ji++) {
            int j = mg * 16 + ji;
            float s = 0.f;
            #pragma unroll 8
            for (int m = 0; m < 64; m++) s += hsm[m * 65 + j] * X[m * 64 + i];
            m1r[ji] = s * (1.0f / 63.0f);
        }
        __syncthreads();
        for (int ji = 0; ji < 16; ji++) X[(mg * 16 + ji) * 64 + i] = m1r[ji];
    }
    __syncthreads();
    // ---- state update ----
    for (int chunk = 0; chunk < 4; chunk++) {
        int n0 = chunk * 64;
        float accv[16];
        #pragma unroll
        for (int l = 0; l < 16; l++) {
            int n = n0 + mg * 16 + l;
            float mn = rowmean[n];
            float a = 0.f;
            #pragma unroll 8
            for (int j = 0; j < 64; j++) a += (ss[n * 64 + j] - mn) * X[j * 64 + i];
            accv[l] = ss[n * 64 + i] + a;
        }
        __syncthreads();
        #pragma unroll
        for (int l = 0; l < 16; l++) {
            int n = n0 + mg * 16 + l;
            ss[n * 64 + i] = accv[l];
            out_state[(size_t)b * 16384 + n * 64 + i] = accv[l];
        }
        __syncthreads();
    }
    // ---- hxi_a, mu, P_a ----
    {
        float acc[16] = {};
        #pragma unroll 4
        for (int n = 0; n < 256; n++) {
            float sv = ss[n * 64 + i];
            #pragma unroll
            for (int mi = 0; mi < 16; mi++)
                acc[mi] += whs[(mg * 16 + mi) * 256 + n] * sv;
        }
        #pragma unroll
        for (int mi = 0; mi < 16; mi++) {
            int m = mg * 16 + mi;
            hsm[m * 65 + i] = acc[mi] + bh[m];
        }
    }
    __syncthreads();
    if (tid < 64) {
        float s = 0.f;
        for (int k = 0; k < 64; k++) s += hsm[tid * 65 + k];
        s *= (1.0f / 64.0f);
        mean_s[tid] = s;
        out_mu[b * 64 + tid] = s;
        float d = y[b * 64 + tid] - s;
        vv[tid] = d; iv[tid] = d;
    }
    __syncthreads();
    for (int idx = tid; idx < 4096; idx += 256) {
        int m = idx >> 6, k = idx & 63;
        hsm[m * 65 + k] -= mean_s[m];
    }
    __syncthreads();
    {
        const int m2 = i;
        for (int mi = 0; mi < 16; mi++) {
            int m = mg * 16 + mi;
            float s = 0.f;
            #pragma unroll 8
            for (int k = 0; k < 64; k++) s += hsm[m * 65 + k] * hsm[m2 * 65 + k];
            float v = s * (1.0f / 63.0f);
            if (m == m2) v += rr;
            Psm[m * 65 + m2] = v;
            out_sig[(size_t)b * 4096 + m * 64 + m2] = v;
        }
    }
    __syncthreads();
    if (tid < 64) Psm[tid * 65 + tid] += 1e-6f;
    __syncthreads();
    chol64_blk(Psm, dinv, tid);
    // ---- vector trisolves + loglik: single warp (R15 proven) ----
    if (tid < 32) {
        const int lane = tid;
        for (int k = 0; k < 64; k++) {
            if (lane == 0) vv[k] *= dinv[k];
            __syncwarp();
            float vk = vv[k];
            for (int r = k + 1 + lane; r < 64; r += 32) vv[r] -= Psm[r * 65 + k] * vk;
            __syncwarp();
        }
        for (int k = 63; k >= 0; k--) {
            if (lane == 0) vv[k] *= dinv[k];
            __syncwarp();
            float vk = vv[k];
            for (int r = lane; r < k; r += 32) vv[r] -= Psm[k * 65 + r] * vk;
            __syncwarp();
        }
        if (lane == 0) {
            float quad = 0.f, ld = 0.f;
            for (int m = 0; m < 64; m++) { quad += iv[m] * vv[m]; ld += __logf(Psm[m * 65 + m]); }
            g_part[b * 2] = quad;
            g_part[b * 2 + 1] = 2.f * ld;
        }
    }
}

__global__ void ek_reduce(float* __restrict__ out) {
    int t = threadIdx.x;
    float q = g_part[t * 2], ld = g_part[t * 2 + 1];
    float l = -0.5f * ld - 0.5f * q;
    #pragma unroll
    for (int s = 16; s; s >>= 1) {
        l += __shfl_xor_sync(0xffffffffu, l, s);
        q += __shfl_xor_sync(0xffffffffu, q, s);
    }
    if (t == 0) { out[0] = l; out[1] = q * (1.0f / 32.0f); }
}

extern "C" void kernel_launch(void* const* d_in, const int* in_sizes, int n_in,
                              void* d_out, int out_size) {
    const float* x    = (const float*)d_in[0];
    const float* y    = (const float*)d_in[1];
    const float* st0  = (const float*)d_in[2];
    const float* Wih  = (const float*)d_in[3];
    const float* Whh  = (const float*)d_in[4];
    const float* bias = (const float*)d_in[5];
    const float* Wh   = (const float*)d_in[6];
    const float* bh   = (const float*)d_in[7];
    const float* q    = (const float*)d_in[8];
    const float* e    = (const float*)d_in[9];
    const float* r    = (const float*)d_in[10];
    const float* eph  = (const float*)d_in[11];
    const float* epc  = (const float*)d_in[12];

    float* out       = (float*)d_out;
    float* out_mu    = out;
    float* out_sig   = out + 2048;
    float* out_state = out + 2048 + 131072;
    float* out_l     = out + 2048 + 131072 + 524288;

    const int SMEM_LSTM = ND * TILEB + 16384 + 256;
    const int SMEM_TAIL = (16384 + 16384 + 4160 + 4160 + 4096 + 64 + 256 + 64 + 64 + 64) * 4;
    static int smem_set = 0;
    if (!smem_set) {
        cudaFuncSetAttribute(ek_lstm, cudaFuncAttributeMaxDynamicSharedMemorySize,
                             SMEM_LSTM);
        cudaFuncSetAttribute(ek_tail, cudaFuncAttributeMaxDynamicSharedMemorySize,
                             SMEM_TAIL);
        smem_set = 1;
    }

    ek_prep<<<768, 256>>>(Whh, x, Wih, bias);
    ek_lstm<<<128, NTHR, SMEM_LSTM>>>(st0, eph, epc, q, e);
    ek_nop<<<1, 32>>>();   // keeps ek_tail in the ncu 4th-launch capture slot
    ek_tail<<<32, 256, SMEM_TAIL>>>(Wh, bh, y, r, out_mu, out_sig, out_state);
    ek_reduce<<<1, 32>>>(out_l);
    (void)in_sizes; (void)n_in; (void)out_size;
}